// round 8
// baseline (speedup 1.0000x reference)
#include <cuda_runtime.h>
#include <cuda_bf16.h>
#include <cstdint>

// 21x21 circular box filter on (8,1,2048,2048) fp32, separable, fused.
// Phase A (horizontal, from GLOBAL): warp per input row; lane does one LDG.128
//   (+1 predicated extras LDG.128), warp prefix scan gives 21-wide box sums,
//   STS.128 to smem. All 8 warps busy, loads fully vectorized, wrap via &2047.
// Phase B (vertical, from SMEM): thread per (column, 16-row half), running sum
//   over smem rows, direct coalesced scalar stores.

#define H  2048
#define W  2048
#define NB 8
#define R  10
#define TX 128
#define TY 32
#define NROWS (TY + 2*R)     // 52 input rows per tile
#define HS 132               // smem h-row stride (floats): 528B, 16B-aligned,
                             // consecutive-c conflict-free for phase B
#define THREADS 256

__global__ __launch_bounds__(THREADS, 6)
void box_filter_kernel(const float* __restrict__ in, float* __restrict__ out)
{
    __shared__ float hbuf[NROWS * HS];   // 52*132*4 = 27,456 B

    const int t    = threadIdx.x;
    const int lane = t & 31;
    const int wp   = t >> 5;

    const int bx = blockIdx.x;
    const int by = blockIdx.y;
    const int bz = blockIdx.z;

    const float* img  = in  + (size_t)bz * (size_t)(H * W);
    float*       outg = out + (size_t)bz * (size_t)(H * W);

    const int tileX = bx * TX;
    const int tileY = by * TY;

    // ------------- Phase A: horizontal box sums (global -> smem) -------------
    // Row basis b[k] = x[(tileX-12+k) & 2047], k=0..151 (38 float4 quads).
    // out_h[m] = sum_{j=-10..10} x[tileX+m+j] = P'[m+23] - P'[m+2],
    // P' = exclusive prefix of b. Lane l holds quad b[4l..4l+3]; lanes 0..5
    // also hold extra quads b[128+4l..] (quad indices 32..37).
    const unsigned FULL = 0xffffffffu;
    // loop-invariant wrapped quad indices (float4 units); float4 never
    // straddles the x-wrap (offsets and 2048 are multiples of 4)
    const int idx0 = ((tileX - 12  + 4 * lane) & (W - 1)) >> 2;
    const int idx1 = ((tileX + 116 + 4 * lane) & (W - 1)) >> 2;

    #pragma unroll 2
    for (int task = wp; task < NROWS; task += THREADS / 32) {
        const int y = (tileY - R + task) & (H - 1);
        const float4* rowp = reinterpret_cast<const float4*>(img + (size_t)y * W);

        float4 q = rowp[idx0];
        float4 eq = make_float4(0.f, 0.f, 0.f, 0.f);
        if (lane < 6) eq = rowp[idx1];

        const float s1 = q.x;
        const float s2 = s1 + q.y;
        const float s3 = s2 + q.z;
        const float s4 = s3 + q.w;

        const float t1 = eq.x;
        const float t2 = t1 + eq.y;
        const float t3 = t2 + eq.z;
        const float t4 = t3 + eq.w;

        // inclusive scan of main quad totals -> v; B = P'[4l]
        float v = s4;
        #pragma unroll
        for (int d = 1; d < 32; d <<= 1) {
            float u = __shfl_up_sync(FULL, v, d);
            if (lane >= d) v += u;
        }
        const float B    = v - s4;
        const float P128 = __shfl_sync(FULL, v, 31);   // P'[128]

        // scan of extra quad totals (6 lanes -> 3 steps); E = exclusive prefix
        float w = t4;
        #pragma unroll
        for (int d = 1; d < 8; d <<= 1) {
            float u = __shfl_up_sync(FULL, w, d);
            if (lane >= d) w += u;
        }
        const float E = w - t4;            // E_m: prefix of extra quads

        // lows: P'[4l+2]=B+s2, P'[4l+3]=B+s3, P'[4l+4]=B_{l+1}, P'[4l+5]=B_{l+1}+s1_{l+1}
        float Bn  = __shfl_down_sync(FULL, B,  1);
        float s1n = __shfl_down_sync(FULL, s1, 1);
        const float t1_0 = __shfl_sync(FULL, t1, 0);
        if (lane == 31) { Bn = P128; s1n = t1_0; }     // quad 32, E_0 = 0

        // highs: quads l+5 (comp3) and l+6 (comp0..2)
        float B5   = __shfl_down_sync(FULL, B,  5);
        float s3_5 = __shfl_down_sync(FULL, s3, 5);
        float B6   = __shfl_down_sync(FULL, B,  6);
        float s1_6 = __shfl_down_sync(FULL, s1, 6);
        float s2_6 = __shfl_down_sync(FULL, s2, 6);

        const float E5x  = __shfl_sync(FULL, E,  lane - 27);
        const float t3_x = __shfl_sync(FULL, t3, lane - 27);
        const float E6x  = __shfl_sync(FULL, E,  lane - 26);
        const float t1_x = __shfl_sync(FULL, t1, lane - 26);
        const float t2_x = __shfl_sync(FULL, t2, lane - 26);
        if (lane >= 27) { B5 = P128 + E5x; s3_5 = t3_x; }
        if (lane >= 26) { B6 = P128 + E6x; s1_6 = t1_x; s2_6 = t2_x; }

        float4 o;
        o.x = (B5 + s3_5) - (B + s2);      // m=4l
        o.y =  B6         - (B + s3);      // m=4l+1
        o.z = (B6 + s1_6) -  Bn;           // m=4l+2
        o.w = (B6 + s2_6) - (Bn + s1n);    // m=4l+3

        *reinterpret_cast<float4*>(hbuf + task * HS + 4 * lane) = o;
    }
    __syncthreads();

    // ------------- Phase B: vertical running sums (smem -> global) -----------
    // Thread = (column c, 16-row half). h rows r0..r0+35 feed outputs r0..r0+15.
    const int c  = t & (TX - 1);
    const int hh = t >> 7;                 // 0 or 1
    const int r0 = hh * 16;
    const float* hcol = hbuf + r0 * HS + c;

    float s = 0.0f;
    #pragma unroll
    for (int j = 0; j < 21; j++) s += hcol[j * HS];

    float* op = outg + (size_t)(tileY + r0) * W + tileX + c;
    op[0] = s;
    #pragma unroll
    for (int i = 1; i < 16; i++) {
        s += hcol[(i + 20) * HS] - hcol[(i - 1) * HS];
        op[i * W] = s;
    }
}

extern "C" void kernel_launch(void* const* d_in, const int* in_sizes, int n_in,
                              void* d_out, int out_size)
{
    const float* x = (const float*)d_in[0];
    float* out = (float*)d_out;

    dim3 grid(W / TX, H / TY, NB);   // (16, 64, 8) = 8192 blocks
    box_filter_kernel<<<grid, THREADS>>>(x, out);
}